// round 15
// baseline (speedup 1.0000x reference)
#include <cuda_runtime.h>
#include <cuda_fp16.h>
#include <math.h>
#include <stdint.h>

// ---------------- problem constants ----------------
#define BATCH 8
#define SEQ   4096
#define F_IN  586
#define KPAD  640
#define DM    512
#define NH    8
#define HD    64
#define FF    1024
#define NLAY  2
#define BS    (BATCH*SEQ)
#define BH    (BATCH*NH)
#define QKVN  (3*DM)
#define EPS_ATTN 1e-6f
#define EPS_LN   1e-5f
#define NCHUNK 8
#define KV_CH  (SEQ/NCHUNK)    // 512
#define KVXR   80              // kv rows: 64 kvT + 1 ks + 15 pad
#define TSTR   136             // staging stride in halves (128 + 8 pad)

// ---------------- scratch ----------------
__device__ __half g_he[BS*KPAD];
__device__ __half g_hx[BS*DM];
__device__ __half g_hy[BS*DM];
__device__ __half g_hq[BS*DM];
__device__ __half g_ht[BS*DM];
__device__ __half g_hh[BS*FF];
__device__ __half g_kT[(size_t)BH*HD*SEQ];
__device__ __half g_vT[(size_t)BH*KVXR*SEQ];
__device__ float  g_kvpart[NCHUNK*BH*KVXR*HD];
__device__ __half g_kvx[BH*KVXR*HD];
__device__ int    g_ctr[BH];            // zero-initialized; self-resetting
__device__ __half g_w0t [DM*KPAD];
__device__ __half g_wqkvt[NLAY*QKVN*DM];
__device__ __half g_wot [NLAY*DM*DM];
__device__ __half g_w1t [NLAY*FF*DM];
__device__ __half g_w2t [NLAY*DM*FF];
__device__ float  g_bqkv[NLAY*QKVN];

// ---------------- helpers ----------------
__device__ __forceinline__ uint32_t smem_u32(const void* p) {
    uint32_t a;
    asm("{ .reg .u64 t; cvta.to.shared.u64 t, %1; cvt.u32.u64 %0, t; }" : "=r"(a) : "l"(p));
    return a;
}
__device__ __forceinline__ void cp_async16(uint32_t dst, const void* src) {
    asm volatile("cp.async.cg.shared.global [%0], [%1], 16;"
                 :: "r"(dst), "l"(src) : "memory");
}
#define CP_COMMIT() asm volatile("cp.async.commit_group;" ::: "memory")
#define CP_WAIT0()  asm volatile("cp.async.wait_group 0;" ::: "memory")

__device__ __forceinline__ void ldmatrix_x4(uint32_t* r, uint32_t addr) {
    asm volatile("ldmatrix.sync.aligned.m8n8.x4.shared.b16 {%0,%1,%2,%3}, [%4];"
                 : "=r"(r[0]), "=r"(r[1]), "=r"(r[2]), "=r"(r[3]) : "r"(addr));
}
__device__ __forceinline__ void mma_f16(float* c, const uint32_t* a, uint32_t b0, uint32_t b1) {
    asm volatile(
        "mma.sync.aligned.m16n8k16.row.col.f32.f16.f16.f32 "
        "{%0,%1,%2,%3}, {%4,%5,%6,%7}, {%8,%9}, {%0,%1,%2,%3};"
        : "+f"(c[0]), "+f"(c[1]), "+f"(c[2]), "+f"(c[3])
        : "r"(a[0]), "r"(a[1]), "r"(a[2]), "r"(a[3]), "r"(b0), "r"(b1));
}

// ---------------- templated fp16 tensor-core GEMM ----------------
// RES: 0 none, 2 = fp16 residual
// OM:  1 = fp16 out (Ch), 3 = qkv split (q -> Ch; k,v -> head-transposed Ch2/Ch3)
#define GBM 128
#define GBN 128
#define TILE_B 16384
#define GEMM_SMEM (4*TILE_B)

template<int KITERS, int N, int ACT, int RES, int OM>
__global__ __launch_bounds__(256) void gemm_t(
    const __half* __restrict__ A, const __half* __restrict__ BT,
    const float* __restrict__ bias, const __half* __restrict__ resh,
    __half* __restrict__ Ch, __half* __restrict__ Ch2, __half* __restrict__ Ch3)
{
    constexpr int K = KITERS * 64;
    extern __shared__ char smraw[];
    const uint32_t smBase = smem_u32(smraw);
    const int tid  = threadIdx.x;
    const int warp = tid >> 5;
    const int lane = tid & 31;
    const int g = lane >> 2;
    const int t = lane & 3;
    const int warpM = warp & 3;
    const int warpN = warp >> 2;
    const int rowBase = blockIdx.y * GBM;
    const int colBase = blockIdx.x * GBN;

    const int ldr = tid >> 3;
    const int ldc = tid & 7;
    auto loadTile = [&](int it, int buf) {
        const int k0 = it * 64;
#pragma unroll
        for (int p = 0; p < 4; p++) {
            int row = p * 32 + ldr;
            uint32_t dst = smBase + buf * TILE_B + row * 128 + ((ldc ^ (row & 7)) << 4);
            cp_async16(dst, &A[(size_t)(rowBase + row) * K + k0 + ldc * 8]);
        }
#pragma unroll
        for (int p = 0; p < 4; p++) {
            int row = p * 32 + ldr;
            uint32_t dst = smBase + 2 * TILE_B + buf * TILE_B + row * 128 + ((ldc ^ (row & 7)) << 4);
            cp_async16(dst, &BT[(size_t)(colBase + row) * K + k0 + ldc * 8]);
        }
    };

    float acc[2][8][4];
#pragma unroll
    for (int mt = 0; mt < 2; mt++)
#pragma unroll
        for (int nt = 0; nt < 8; nt++)
#pragma unroll
            for (int i = 0; i < 4; i++) acc[mt][nt][i] = 0.f;

    loadTile(0, 0);
    CP_COMMIT();

    const int lrow = lane & 15;
    const int khalf = lane >> 4;

#pragma unroll 1
    for (int it = 0; it < KITERS; ++it) {
        const int buf = it & 1;
        CP_WAIT0();
        __syncthreads();
        if (it + 1 < KITERS) {
            loadTile(it + 1, buf ^ 1);
            CP_COMMIT();
        }
        const uint32_t Abase = smBase + buf * TILE_B;
        const uint32_t Bbase = smBase + 2 * TILE_B + buf * TILE_B;
#pragma unroll
        for (int ks = 0; ks < 4; ks++) {
            const int cIdx = 2 * ks + khalf;
            uint32_t a[2][4];
#pragma unroll
            for (int mt = 0; mt < 2; mt++) {
                int row = warpM * 32 + mt * 16 + lrow;
                ldmatrix_x4(a[mt], Abase + row * 128 + ((cIdx ^ (row & 7)) << 4));
            }
            uint32_t br[4][4];
#pragma unroll
            for (int j = 0; j < 4; j++) {
                int row = warpN * 64 + j * 16 + lrow;
                ldmatrix_x4(br[j], Bbase + row * 128 + ((cIdx ^ (row & 7)) << 4));
            }
#pragma unroll
            for (int mt = 0; mt < 2; mt++)
#pragma unroll
                for (int j = 0; j < 4; j++) {
                    mma_f16(acc[mt][2 * j],     a[mt], br[j][0], br[j][2]);
                    mma_f16(acc[mt][2 * j + 1], a[mt], br[j][1], br[j][3]);
                }
        }
    }

    // ---- epilogue ----
    const bool stage = (OM == 3) && (colBase >= 512);
    __half* sh = (__half*)smraw;
    if (stage) __syncthreads();

#pragma unroll
    for (int mt = 0; mt < 2; mt++) {
#pragma unroll
        for (int sub = 0; sub < 2; sub++) {
            const int rl = warpM * 32 + mt * 16 + g + sub * 8;
            const int r = rowBase + rl;
#pragma unroll
            for (int nt = 0; nt < 8; nt++) {
                const int cl = warpN * 64 + nt * 8 + 2 * t;
                const int c = colBase + cl;
                float2 o;
                o.x = acc[mt][nt][sub * 2 + 0];
                o.y = acc[mt][nt][sub * 2 + 1];
                float2 bi = *(const float2*)&bias[c];
                o.x += bi.x; o.y += bi.y;
                if (RES == 2) {
                    float2 rr = __half22float2(*(const __half2*)&resh[(size_t)r * N + c]);
                    o.x += rr.x; o.y += rr.y;
                }
                if (ACT == 1 || (ACT == 3 && c < 2 * DM)) {
                    o.x = (o.x > 0.f) ? (o.x + 1.f) : expf(o.x);
                    o.y = (o.y > 0.f) ? (o.y + 1.f) : expf(o.y);
                } else if (ACT == 2) {
                    o.x = fmaxf(o.x, 0.f);
                    o.y = fmaxf(o.y, 0.f);
                }
                if (OM == 3) {
                    if (!stage) {
                        *(__half2*)&Ch[(size_t)r * DM + c] = __floats2half2_rn(o.x, o.y);
                    } else {
                        sh[cl * TSTR + rl]       = __float2half(o.x);
                        sh[(cl + 1) * TSTR + rl] = __float2half(o.y);
                    }
                } else {
                    *(__half2*)&Ch[(size_t)r * N + c] = __floats2half2_rn(o.x, o.y);
                }
            }
        }
    }

    if (stage) {
        __syncthreads();
        const int seg = colBase >> 9;          // 1 = k, 2 = v
        const int rowd = tid >> 1;
        const int hs = tid & 1;
        const int hloc = rowd >> 6, d = rowd & 63;
        const int b = rowBase >> 12;
        const int s0 = rowBase & (SEQ - 1);
        const int hbase = (colBase & 511) >> 6;
        const int bh = b * NH + hbase + hloc;
        __half* dstT = (seg == 1) ? Ch2 : Ch3;
        const size_t rstr = (seg == 1) ? HD : KVXR;
        const uint4* s4 = (const uint4*)(sh + rowd * TSTR + hs * 64);
        uint4* d4 = (uint4*)(dstT + ((size_t)bh * rstr + d) * SEQ + s0 + hs * 64);
#pragma unroll
        for (int i = 0; i < 8; i++) d4[i] = s4[i];
    }
}

// ---------------- pad embeddings ----------------
__global__ void pad_emb_h(const float* __restrict__ in, __half* __restrict__ out) {
    int i = blockIdx.x * 256 + threadIdx.x;
    if (i >= BS * KPAD) return;
    int r = i / KPAD, c = i - r * KPAD;
    out[i] = (c < F_IN) ? __float2half(in[(size_t)r * F_IN + c]) : __half(0.f);
}

// ---------------- init vT tail rows ----------------
__global__ void init_vtail(__half* __restrict__ vT) {
    int i = blockIdx.x * 256 + threadIdx.x;
    if (i >= BH * 16 * SEQ) return;
    int bh = i / (16 * SEQ);
    int rem = i - bh * 16 * SEQ;
    int row = 64 + rem / SEQ;
    int s = rem % SEQ;
    vT[((size_t)bh * KVXR + row) * SEQ + s] = (row == 64) ? __half(1.f) : __half(0.f);
}

// ---------------- batched weight transpose ----------------
#define NTR 13
struct TrDesc { const float* in; __half* out; int K; int N; int KP; int tileStart; };
struct TrPack { TrDesc d[NTR]; };

__global__ void transpose_batch(TrPack p) {
    __shared__ float t[32][33];
    const int bt = blockIdx.x;
    int mi = 0;
#pragma unroll
    for (int i = 1; i < NTR; i++)
        if (bt >= p.d[i].tileStart) mi = i;
    const TrDesc de = p.d[mi];
    const int lt = bt - de.tileStart;
    const int ktiles = de.KP >> 5;
    const int k0 = (lt % ktiles) * 32;
    const int n0 = (lt / ktiles) * 32;
    const int x = threadIdx.x, y = threadIdx.y;
#pragma unroll
    for (int j = 0; j < 32; j += 8) {
        int kk = k0 + y + j;
        t[y + j][x] = (kk < de.K && n0 + x < de.N)
                      ? de.in[(size_t)kk * de.N + n0 + x] : 0.f;
    }
    __syncthreads();
#pragma unroll
    for (int j = 0; j < 32; j += 8)
        if (n0 + y + j < de.N)
            de.out[(size_t)(n0 + y + j) * de.KP + k0 + x] = __float2half(t[x][y + j]);
}

// ---------------- concat q/k/v biases ----------------
__global__ void concat_bias(const float* __restrict__ bq, const float* __restrict__ bk,
                            const float* __restrict__ bv, float* __restrict__ out) {
    int i = blockIdx.x * 256 + threadIdx.x;
    if (i >= NLAY * QKVN) return;
    int l = i / QKVN, c = i - l * QKVN;
    float v;
    if (c < DM)           v = bq[l * DM + c];
    else if (c < 2 * DM)  v = bk[l * DM + c - DM];
    else                  v = bv[l * DM + c - 2 * DM];
    out[i] = v;
}

// ---------------- kv partials via mma + last-CTA deterministic reduction ----------------
__global__ __launch_bounds__(128) void kv_mma(
    const __half* __restrict__ kT, const __half* __restrict__ vT,
    float* __restrict__ kvpart, __half* __restrict__ kvx, int* __restrict__ ctr)
{
    __shared__ __half smA[2][KVXR * 64];
    __shared__ __half smB[2][64 * 64];
    const uint32_t aBase0 = smem_u32(smA);
    const uint32_t bBase0 = smem_u32(smB);
    const int bh = blockIdx.x;
    const int chunk = blockIdx.y;
    const int tid = threadIdx.x;
    const int warp = tid >> 5;
    const int lane = tid & 31;
    const int g = lane >> 2, t = lane & 3;
    const int lrow = lane & 15, khalf = lane >> 4;
    const int s0 = chunk * KV_CH;

    const int ldr = tid >> 3;
    const int ldc = tid & 7;
    auto loadTile = [&](int it, int buf) {
        const int k0 = s0 + it * 64;
#pragma unroll
        for (int p = 0; p < 5; p++) {
            int row = p * 16 + ldr;
            uint32_t off = buf * (KVXR * 128) + row * 128 + ((ldc ^ (row & 7)) << 4);
            cp_async16(aBase0 + off, &vT[((size_t)bh * KVXR + row) * SEQ + k0 + ldc * 8]);
        }
#pragma unroll
        for (int p = 0; p < 4; p++) {
            int row = p * 16 + ldr;
            uint32_t off = buf * 8192 + row * 128 + ((ldc ^ (row & 7)) << 4);
            cp_async16(bBase0 + off, &kT[((size_t)bh * HD + row) * SEQ + k0 + ldc * 8]);
        }
    };

    float acc[5][2][4];
#pragma unroll
    for (int mt = 0; mt < 5; mt++)
#pragma unroll
        for (int j = 0; j < 2; j++)
#pragma unroll
            for (int i = 0; i < 4; i++) acc[mt][j][i] = 0.f;

    loadTile(0, 0);
    CP_COMMIT();

#pragma unroll 1
    for (int it = 0; it < KV_CH / 64; ++it) {
        const int buf = it & 1;
        CP_WAIT0();
        __syncthreads();
        if (it + 1 < KV_CH / 64) {
            loadTile(it + 1, buf ^ 1);
            CP_COMMIT();
        }
        const uint32_t Ab = aBase0 + buf * (KVXR * 128);
        const uint32_t Bb = bBase0 + buf * 8192;
#pragma unroll
        for (int ks = 0; ks < 4; ks++) {
            const int cIdx = 2 * ks + khalf;
            uint32_t a[5][4];
#pragma unroll
            for (int mt = 0; mt < 5; mt++) {
                int row = mt * 16 + lrow;
                ldmatrix_x4(a[mt], Ab + row * 128 + ((cIdx ^ (row & 7)) << 4));
            }
            uint32_t br[4];
            {
                int row = warp * 16 + lrow;
                ldmatrix_x4(br, Bb + row * 128 + ((cIdx ^ (row & 7)) << 4));
            }
#pragma unroll
            for (int mt = 0; mt < 5; mt++) {
                mma_f16(acc[mt][0], a[mt], br[0], br[2]);
                mma_f16(acc[mt][1], a[mt], br[1], br[3]);
            }
        }
    }

#pragma unroll
    for (int mt = 0; mt < 5; mt++)
#pragma unroll
        for (int j = 0; j < 2; j++)
#pragma unroll
            for (int sub = 0; sub < 2; sub++) {
                int m = mt * 16 + g + sub * 8;
                int d = warp * 16 + j * 8 + 2 * t;
                float2 o;
                o.x = acc[mt][j][sub * 2 + 0];
                o.y = acc[mt][j][sub * 2 + 1];
                *(float2*)&kvpart[(((size_t)chunk * BH + bh) * KVXR + m) * HD + d] = o;
            }

    // last-arriving CTA for this bh reduces all chunks (fixed order -> deterministic)
    __threadfence();
    __shared__ int isLast;
    if (tid == 0) {
        int old = atomicAdd(&ctr[bh], 1);
        isLast = (old == NCHUNK - 1) ? 1 : 0;
    }
    __syncthreads();
    if (isLast) {
        for (int idx = tid; idx < KVXR * HD; idx += 128) {
            float v = 0.f;
#pragma unroll
            for (int c = 0; c < NCHUNK; c++)
                v += kvpart[((size_t)c * BH + bh) * (KVXR * HD) + idx];
            kvx[(size_t)bh * (KVXR * HD) + idx] = __float2half(v);
        }
        if (tid == 0) ctr[bh] = 0;     // self-reset for next layer / replay
    }
}

// ---------------- attention via mma: 256 thr, 128 tokens/CTA ----------------
__global__ __launch_bounds__(256) void attn_mma(
    const __half* __restrict__ q, const __half* __restrict__ kvx,
    __half* __restrict__ out)
{
    __shared__ __half smA[128 * 64];    // q tile (128 tokens)
    __shared__ __half smB[KVXR * 64];   // kvx
    const uint32_t aBase = smem_u32(smA);
    const uint32_t bBase = smem_u32(smB);
    const int bh = blockIdx.x;
    const int s0 = blockIdx.y * 128;
    const int b = bh >> 3, h = bh & 7;
    const int tid = threadIdx.x;
    const int warp = tid >> 5;          // 0..7, each owns 16 tokens
    const int lane = tid & 31;
    const int g = lane >> 2, t = lane & 3;
    const int lrow = lane & 15, khalf = lane >> 4;

    {
        const int ldr = tid >> 3, ldc = tid & 7;
#pragma unroll
        for (int p = 0; p < 4; p++) {          // q: 128 rows
            int row = p * 32 + ldr;
            uint32_t dst = aBase + row * 128 + ((ldc ^ (row & 7)) << 4);
            cp_async16(dst, &q[(size_t)(b * SEQ + s0 + row) * DM + h * HD + ldc * 8]);
        }
#pragma unroll
        for (int p = 0; p < 3; p++) {          // kvx: 80 rows
            int row = p * 32 + ldr;
            if (row < KVXR) {
                uint32_t dst = bBase + row * 128 + ((ldc ^ (row & 7)) << 4);
                cp_async16(dst, &kvx[((size_t)bh * KVXR + row) * HD + ldc * 8]);
            }
        }
        CP_COMMIT();
        CP_WAIT0();
        __syncthreads();
    }

    float acc[10][4];
#pragma unroll
    for (int nt = 0; nt < 10; nt++)
#pragma unroll
        for (int i = 0; i < 4; i++) acc[nt][i] = 0.f;

#pragma unroll
    for (int ks = 0; ks < 4; ks++) {
        const int cIdx = 2 * ks + khalf;
        uint32_t a[4];
        {
            int row = warp * 16 + lrow;
            ldmatrix_x4(a, aBase + row * 128 + ((cIdx ^ (row & 7)) << 4));
        }
#pragma unroll
        for (int j = 0; j < 5; j++) {
            uint32_t br[4];
            int row = j * 16 + lrow;
            ldmatrix_x4(br, bBase + row * 128 + ((cIdx ^ (row & 7)) << 4));
            mma_f16(acc[2 * j],     a, br[0], br[2]);
            mma_f16(acc[2 * j + 1], a, br[1], br[3]);
        }
    }

    float d0 = __shfl_sync(0xffffffffu, acc[8][0], lane & 28);
    float d1 = __shfl_sync(0xffffffffu, acc[8][2], lane & 28);
    float z0 = 1.f / (d0 + EPS_ATTN);
    float z1 = 1.f / (d1 + EPS_ATTN);

    const int r0 = s0 + warp * 16 + g;
#pragma unroll
    for (int nt = 0; nt < 8; nt++) {
        int c = nt * 8 + 2 * t;
        *(__half2*)&out[(size_t)(b * SEQ + r0) * DM + h * HD + c] =
            __floats2half2_rn(acc[nt][0] * z0, acc[nt][1] * z0);
        *(__half2*)&out[(size_t)(b * SEQ + r0 + 8) * DM + h * HD + c] =
            __floats2half2_rn(acc[nt][2] * z1, acc[nt][3] * z1);
    }
}

// ---------------- block reduce helper ----------------
__device__ __forceinline__ float bsum128(float v, float* sm) {
#pragma unroll
    for (int o = 16; o > 0; o >>= 1) v += __shfl_down_sync(0xffffffffu, v, o);
    int w = threadIdx.x >> 5;
    if ((threadIdx.x & 31) == 0) sm[w] = v;
    __syncthreads();
    float r = sm[0] + sm[1] + sm[2] + sm[3];
    __syncthreads();
    return r;
}

// ---------------- layernorm: fp16 in -> fp16 out ----------------
__global__ __launch_bounds__(128) void ln_kernel(
    const __half* __restrict__ in, const float* __restrict__ g,
    const float* __restrict__ b, __half* __restrict__ hout)
{
    __shared__ float sm[4];
    const int row = blockIdx.x;
    const int tid = threadIdx.x;
    uint2 raw = ((const uint2*)(in + (size_t)row * DM))[tid];
    float2 f0 = __half22float2(*(__half2*)&raw.x);
    float2 f1 = __half22float2(*(__half2*)&raw.y);
    float s  = f0.x + f0.y + f1.x + f1.y;
    float sq = f0.x * f0.x + f0.y * f0.y + f1.x * f1.x + f1.y * f1.y;
    s  = bsum128(s, sm);
    sq = bsum128(sq, sm);
    float mu = s * (1.f / DM);
    float var = sq * (1.f / DM) - mu * mu;
    float rstd = rsqrtf(var + EPS_LN);
    float4 gg = ((const float4*)g)[tid];
    float4 bb = ((const float4*)b)[tid];
    float ox = (f0.x - mu) * rstd * gg.x + bb.x;
    float oy = (f0.y - mu) * rstd * gg.y + bb.y;
    float oz = (f1.x - mu) * rstd * gg.z + bb.z;
    float ow = (f1.y - mu) * rstd * gg.w + bb.w;
    uint2 pk;
    *(__half2*)&pk.x = __floats2half2_rn(ox, oy);
    *(__half2*)&pk.y = __floats2half2_rn(oz, ow);
    ((uint2*)(hout + (size_t)row * DM))[tid] = pk;
}

// ---------------- fused final LN + out proj (fp16 in) ----------------
__global__ __launch_bounds__(128) void final_kernel(
    const __half* __restrict__ in, const float* __restrict__ g,
    const float* __restrict__ b, const float* __restrict__ w,
    const float* __restrict__ bout, float* __restrict__ out)
{
    __shared__ float sm[4];
    const int row = blockIdx.x;
    const int tid = threadIdx.x;
    uint2 raw = ((const uint2*)(in + (size_t)row * DM))[tid];
    float2 f0 = __half22float2(*(__half2*)&raw.x);
    float2 f1 = __half22float2(*(__half2*)&raw.y);
    float s  = f0.x + f0.y + f1.x + f1.y;
    float sq = f0.x * f0.x + f0.y * f0.y + f1.x * f1.x + f1.y * f1.y;
    s  = bsum128(s, sm);
    sq = bsum128(sq, sm);
    float mu = s * (1.f / DM);
    float var = sq * (1.f / DM) - mu * mu;
    float rstd = rsqrtf(var + EPS_LN);
    float4 gg = ((const float4*)g)[tid];
    float4 bb = ((const float4*)b)[tid];
    float4 ww = ((const float4*)w)[tid];
    float acc = ((f0.x - mu) * rstd * gg.x + bb.x) * ww.x
              + ((f0.y - mu) * rstd * gg.y + bb.y) * ww.y
              + ((f1.x - mu) * rstd * gg.z + bb.z) * ww.z
              + ((f1.y - mu) * rstd * gg.w + bb.w) * ww.w;
    acc = bsum128(acc, sm);
    if (tid == 0) out[row] = acc + bout[0];
}

extern "C" void kernel_launch(void* const* d_in, const int* in_sizes, int n_in,
                              void* d_out, int out_size)
{
    const float* emb   = (const float*)d_in[0];
    const float* W0    = (const float*)d_in[1];
    const float* b0    = (const float*)d_in[2];
    const float* Wq    = (const float*)d_in[3];
    const float* bq    = (const float*)d_in[4];
    const float* Wk    = (const float*)d_in[5];
    const float* bk    = (const float*)d_in[6];
    const float* Wv    = (const float*)d_in[7];
    const float* bv    = (const float*)d_in[8];
    const float* Wo    = (const float*)d_in[9];
    const float* bo    = (const float*)d_in[10];
    const float* ln1s  = (const float*)d_in[11];
    const float* ln1b  = (const float*)d_in[12];
    const float* W1    = (const float*)d_in[13];
    const float* b1    = (const float*)d_in[14];
    const float* W2    = (const float*)d_in[15];
    const float* b2    = (const float*)d_in[16];
    const float* ln2s  = (const float*)d_in[17];
    const float* ln2b  = (const float*)d_in[18];
    const float* lnfs  = (const float*)d_in[19];
    const float* lnfb  = (const float*)d_in[20];
    const float* Wout  = (const float*)d_in[21];
    const float* bout  = (const float*)d_in[22];
    float* out = (float*)d_out;

    auto gemm_in   = gemm_t<10, DM,   0, 0, 1>;
    auto gemm_qkv  = gemm_t<8,  QKVN, 3, 0, 3>;
    auto gemm_wo   = gemm_t<8,  DM,   0, 2, 1>;
    auto gemm_ffn1 = gemm_t<8,  FF,   2, 0, 1>;
    auto gemm_ffn2 = gemm_t<16, DM,   0, 2, 1>;
    cudaFuncSetAttribute(gemm_in,   cudaFuncAttributeMaxDynamicSharedMemorySize, GEMM_SMEM);
    cudaFuncSetAttribute(gemm_qkv,  cudaFuncAttributeMaxDynamicSharedMemorySize, GEMM_SMEM);
    cudaFuncSetAttribute(gemm_wo,   cudaFuncAttributeMaxDynamicSharedMemorySize, GEMM_SMEM);
    cudaFuncSetAttribute(gemm_ffn1, cudaFuncAttributeMaxDynamicSharedMemorySize, GEMM_SMEM);
    cudaFuncSetAttribute(gemm_ffn2, cudaFuncAttributeMaxDynamicSharedMemorySize, GEMM_SMEM);

    __half *he, *hx, *hy, *hq, *ht, *hh, *kT, *vT, *kvx;
    __half *w0t, *wqkvt, *wot, *w1t, *w2t;
    float *pkvp, *bqkv;
    int *ctr;
    cudaGetSymbolAddress((void**)&he,  g_he);
    cudaGetSymbolAddress((void**)&hx,  g_hx);
    cudaGetSymbolAddress((void**)&hy,  g_hy);
    cudaGetSymbolAddress((void**)&hq,  g_hq);
    cudaGetSymbolAddress((void**)&ht,  g_ht);
    cudaGetSymbolAddress((void**)&hh,  g_hh);
    cudaGetSymbolAddress((void**)&kT,  g_kT);
    cudaGetSymbolAddress((void**)&vT,  g_vT);
    cudaGetSymbolAddress((void**)&kvx, g_kvx);
    cudaGetSymbolAddress((void**)&pkvp, g_kvpart);
    cudaGetSymbolAddress((void**)&ctr, g_ctr);
    cudaGetSymbolAddress((void**)&w0t, g_w0t);
    cudaGetSymbolAddress((void**)&wqkvt, g_wqkvt);
    cudaGetSymbolAddress((void**)&wot, g_wot);
    cudaGetSymbolAddress((void**)&w1t, g_w1t);
    cudaGetSymbolAddress((void**)&w2t, g_w2t);
    cudaGetSymbolAddress((void**)&bqkv, g_bqkv);

    // ---- prep ----
    pad_emb_h<<<(BS * KPAD + 255) / 256, 256>>>(emb, he);
    concat_bias<<<(NLAY * QKVN + 255) / 256, 256>>>(bq, bk, bv, bqkv);
    init_vtail<<<(BH * 16 * SEQ + 255) / 256, 256>>>(vT);

    TrPack pack;
    int tileOff = 0;
    auto addTr = [&](int idx, const float* in, __half* outp, int K, int N, int KP) {
        pack.d[idx].in = in; pack.d[idx].out = outp;
        pack.d[idx].K = K; pack.d[idx].N = N; pack.d[idx].KP = KP;
        pack.d[idx].tileStart = tileOff;
        tileOff += (KP / 32) * ((N + 31) / 32);
    };
    int di = 0;
    addTr(di++, W0, w0t, F_IN, DM, KPAD);
    for (int l = 0; l < NLAY; l++) {
        __half* wl = wqkvt + (size_t)l * QKVN * DM;
        addTr(di++, Wq + (size_t)l * DM * DM, wl,                        DM, DM, DM);
        addTr(di++, Wk + (size_t)l * DM * DM, wl + (size_t)DM * DM,      DM, DM, DM);
        addTr(di++, Wv + (size_t)l * DM * DM, wl + (size_t)2 * DM * DM,  DM, DM, DM);
        addTr(di++, Wo + (size_t)l * DM * DM, wot + (size_t)l * DM * DM, DM, DM, DM);
        addTr(di++, W1 + (size_t)l * DM * FF, w1t + (size_t)l * DM * FF, DM, FF, DM);
        addTr(di++, W2 + (size_t)l * FF * DM, w2t + (size_t)l * FF * DM, FF, DM, FF);
    }
    transpose_batch<<<tileOff, dim3(32, 8)>>>(pack);

    // ---- input projection -> hx fp16 ----
    gemm_in<<<dim3(DM / GBN, BS / GBM), 256, GEMM_SMEM>>>(
        he, w0t, b0, nullptr, hx, nullptr, nullptr);

    for (int l = 0; l < NLAY; l++) {
        const __half* wqkv_l = wqkvt + (size_t)l * QKVN * DM;
        const __half* wot_l  = wot + (size_t)l * DM * DM;
        const __half* w1t_l  = w1t + (size_t)l * DM * FF;
        const __half* w2t_l  = w2t + (size_t)l * FF * DM;
        const float* bqkv_l = bqkv + (size_t)l * QKVN;
        const float* bo_l = bo + (size_t)l * DM;
        const float* b1_l = b1 + (size_t)l * FF;
        const float* b2_l = b2 + (size_t)l * DM;

        gemm_qkv<<<dim3(QKVN / GBN, BS / GBM), 256, GEMM_SMEM>>>(
            hx, wqkv_l, bqkv_l, nullptr, hq, kT, vT);

        kv_mma<<<dim3(BH, NCHUNK), 128>>>(kT, vT, pkvp, kvx, ctr);
        attn_mma<<<dim3(BH, SEQ / 128), 256>>>(hq, kvx, ht);

        gemm_wo<<<dim3(DM / GBN, BS / GBM), 256, GEMM_SMEM>>>(
            ht, wot_l, bo_l, hx, hy, nullptr, nullptr);
        ln_kernel<<<BS, 128>>>(hy, ln1s + (size_t)l * DM, ln1b + (size_t)l * DM, hx);

        gemm_ffn1<<<dim3(FF / GBN, BS / GBM), 256, GEMM_SMEM>>>(
            hx, w1t_l, b1_l, nullptr, hh, nullptr, nullptr);
        gemm_ffn2<<<dim3(DM / GBN, BS / GBM), 256, GEMM_SMEM>>>(
            hh, w2t_l, b2_l, hx, hy, nullptr, nullptr);
        ln_kernel<<<BS, 128>>>(hy, ln2s + (size_t)l * DM, ln2b + (size_t)l * DM, hx);
    }

    final_kernel<<<BS, 128>>>(hx, lnfs, lnfb, Wout, bout, out);
}

// round 16
// speedup vs baseline: 1.0191x; 1.0191x over previous
#include <cuda_runtime.h>
#include <cuda_fp16.h>
#include <math.h>
#include <stdint.h>

// ---------------- problem constants ----------------
#define BATCH 8
#define SEQ   4096
#define F_IN  586
#define KPAD  640
#define DM    512
#define NH    8
#define HD    64
#define FF    1024
#define NLAY  2
#define BS    (BATCH*SEQ)
#define BH    (BATCH*NH)
#define QKVN  (3*DM)
#define EPS_ATTN 1e-6f
#define EPS_LN   1e-5f
#define NCHUNK 8
#define KV_CH  (SEQ/NCHUNK)    // 512
#define KVXR   80              // kv rows: 64 kvT + 1 ks + 15 pad
#define TSTR   136             // staging stride in halves (128 + 8 pad)

// ---------------- scratch ----------------
__device__ __half g_he[BS*KPAD];
__device__ __half g_hx[BS*DM];
__device__ __half g_hy[BS*DM];
__device__ __half g_hq[BS*DM];
__device__ __half g_ht[BS*DM];
__device__ __half g_hh[BS*FF];
__device__ __half g_kT[(size_t)BH*HD*SEQ];
__device__ __half g_vT[(size_t)BH*KVXR*SEQ];
__device__ float  g_kvpart[NCHUNK*BH*KVXR*HD];
__device__ __half g_kvx[BH*KVXR*HD];
__device__ __half g_w0t [DM*KPAD];
__device__ __half g_wqkvt[NLAY*QKVN*DM];
__device__ __half g_wot [NLAY*DM*DM];
__device__ __half g_w1t [NLAY*FF*DM];
__device__ __half g_w2t [NLAY*DM*FF];
__device__ float  g_bqkv[NLAY*QKVN];

// ---------------- helpers ----------------
__device__ __forceinline__ uint32_t smem_u32(const void* p) {
    uint32_t a;
    asm("{ .reg .u64 t; cvta.to.shared.u64 t, %1; cvt.u32.u64 %0, t; }" : "=r"(a) : "l"(p));
    return a;
}
__device__ __forceinline__ void cp_async16(uint32_t dst, const void* src) {
    asm volatile("cp.async.cg.shared.global [%0], [%1], 16;"
                 :: "r"(dst), "l"(src) : "memory");
}
#define CP_COMMIT() asm volatile("cp.async.commit_group;" ::: "memory")
#define CP_WAIT0()  asm volatile("cp.async.wait_group 0;" ::: "memory")

__device__ __forceinline__ void ldmatrix_x4(uint32_t* r, uint32_t addr) {
    asm volatile("ldmatrix.sync.aligned.m8n8.x4.shared.b16 {%0,%1,%2,%3}, [%4];"
                 : "=r"(r[0]), "=r"(r[1]), "=r"(r[2]), "=r"(r[3]) : "r"(addr));
}
__device__ __forceinline__ void mma_f16(float* c, const uint32_t* a, uint32_t b0, uint32_t b1) {
    asm volatile(
        "mma.sync.aligned.m16n8k16.row.col.f32.f16.f16.f32 "
        "{%0,%1,%2,%3}, {%4,%5,%6,%7}, {%8,%9}, {%0,%1,%2,%3};"
        : "+f"(c[0]), "+f"(c[1]), "+f"(c[2]), "+f"(c[3])
        : "r"(a[0]), "r"(a[1]), "r"(a[2]), "r"(a[3]), "r"(b0), "r"(b1));
}

// ---------------- templated fp16 tensor-core GEMM ----------------
// RES: 0 none, 2 = fp16 residual
// OM:  1 = fp16 out (Ch), 3 = qkv split (q -> Ch; k,v -> head-transposed Ch2/Ch3)
#define GBM 128
#define GBN 128
#define TILE_B 16384
#define GEMM_SMEM (4*TILE_B)

template<int KITERS, int N, int ACT, int RES, int OM>
__global__ __launch_bounds__(256) void gemm_t(
    const __half* __restrict__ A, const __half* __restrict__ BT,
    const float* __restrict__ bias, const __half* __restrict__ resh,
    __half* __restrict__ Ch, __half* __restrict__ Ch2, __half* __restrict__ Ch3)
{
    constexpr int K = KITERS * 64;
    extern __shared__ char smraw[];
    const uint32_t smBase = smem_u32(smraw);
    const int tid  = threadIdx.x;
    const int warp = tid >> 5;
    const int lane = tid & 31;
    const int g = lane >> 2;
    const int t = lane & 3;
    const int warpM = warp & 3;
    const int warpN = warp >> 2;
    const int rowBase = blockIdx.y * GBM;
    const int colBase = blockIdx.x * GBN;

    const int ldr = tid >> 3;
    const int ldc = tid & 7;
    auto loadTile = [&](int it, int buf) {
        const int k0 = it * 64;
#pragma unroll
        for (int p = 0; p < 4; p++) {
            int row = p * 32 + ldr;
            uint32_t dst = smBase + buf * TILE_B + row * 128 + ((ldc ^ (row & 7)) << 4);
            cp_async16(dst, &A[(size_t)(rowBase + row) * K + k0 + ldc * 8]);
        }
#pragma unroll
        for (int p = 0; p < 4; p++) {
            int row = p * 32 + ldr;
            uint32_t dst = smBase + 2 * TILE_B + buf * TILE_B + row * 128 + ((ldc ^ (row & 7)) << 4);
            cp_async16(dst, &BT[(size_t)(colBase + row) * K + k0 + ldc * 8]);
        }
    };

    float acc[2][8][4];
#pragma unroll
    for (int mt = 0; mt < 2; mt++)
#pragma unroll
        for (int nt = 0; nt < 8; nt++)
#pragma unroll
            for (int i = 0; i < 4; i++) acc[mt][nt][i] = 0.f;

    loadTile(0, 0);
    CP_COMMIT();

    const int lrow = lane & 15;
    const int khalf = lane >> 4;

#pragma unroll 1
    for (int it = 0; it < KITERS; ++it) {
        const int buf = it & 1;
        CP_WAIT0();
        __syncthreads();
        if (it + 1 < KITERS) {
            loadTile(it + 1, buf ^ 1);
            CP_COMMIT();
        }
        const uint32_t Abase = smBase + buf * TILE_B;
        const uint32_t Bbase = smBase + 2 * TILE_B + buf * TILE_B;
#pragma unroll
        for (int ks = 0; ks < 4; ks++) {
            const int cIdx = 2 * ks + khalf;
            uint32_t a[2][4];
#pragma unroll
            for (int mt = 0; mt < 2; mt++) {
                int row = warpM * 32 + mt * 16 + lrow;
                ldmatrix_x4(a[mt], Abase + row * 128 + ((cIdx ^ (row & 7)) << 4));
            }
            uint32_t br[4][4];
#pragma unroll
            for (int j = 0; j < 4; j++) {
                int row = warpN * 64 + j * 16 + lrow;
                ldmatrix_x4(br[j], Bbase + row * 128 + ((cIdx ^ (row & 7)) << 4));
            }
#pragma unroll
            for (int mt = 0; mt < 2; mt++)
#pragma unroll
                for (int j = 0; j < 4; j++) {
                    mma_f16(acc[mt][2 * j],     a[mt], br[j][0], br[j][2]);
                    mma_f16(acc[mt][2 * j + 1], a[mt], br[j][1], br[j][3]);
                }
        }
    }

    // ---- epilogue ----
    const bool stage = (OM == 3) && (colBase >= 512);
    __half* sh = (__half*)smraw;
    if (stage) __syncthreads();

#pragma unroll
    for (int mt = 0; mt < 2; mt++) {
#pragma unroll
        for (int sub = 0; sub < 2; sub++) {
            const int rl = warpM * 32 + mt * 16 + g + sub * 8;
            const int r = rowBase + rl;
#pragma unroll
            for (int nt = 0; nt < 8; nt++) {
                const int cl = warpN * 64 + nt * 8 + 2 * t;
                const int c = colBase + cl;
                float2 o;
                o.x = acc[mt][nt][sub * 2 + 0];
                o.y = acc[mt][nt][sub * 2 + 1];
                float2 bi = *(const float2*)&bias[c];
                o.x += bi.x; o.y += bi.y;
                if (RES == 2) {
                    float2 rr = __half22float2(*(const __half2*)&resh[(size_t)r * N + c]);
                    o.x += rr.x; o.y += rr.y;
                }
                if (ACT == 1 || (ACT == 3 && c < 2 * DM)) {
                    o.x = (o.x > 0.f) ? (o.x + 1.f) : expf(o.x);
                    o.y = (o.y > 0.f) ? (o.y + 1.f) : expf(o.y);
                } else if (ACT == 2) {
                    o.x = fmaxf(o.x, 0.f);
                    o.y = fmaxf(o.y, 0.f);
                }
                if (OM == 3) {
                    if (!stage) {
                        *(__half2*)&Ch[(size_t)r * DM + c] = __floats2half2_rn(o.x, o.y);
                    } else {
                        sh[cl * TSTR + rl]       = __float2half(o.x);
                        sh[(cl + 1) * TSTR + rl] = __float2half(o.y);
                    }
                } else {
                    *(__half2*)&Ch[(size_t)r * N + c] = __floats2half2_rn(o.x, o.y);
                }
            }
        }
    }

    if (stage) {
        __syncthreads();
        const int seg = colBase >> 9;          // 1 = k, 2 = v
        const int rowd = tid >> 1;
        const int hs = tid & 1;
        const int hloc = rowd >> 6, d = rowd & 63;
        const int b = rowBase >> 12;
        const int s0 = rowBase & (SEQ - 1);
        const int hbase = (colBase & 511) >> 6;
        const int bh = b * NH + hbase + hloc;
        __half* dstT = (seg == 1) ? Ch2 : Ch3;
        const size_t rstr = (seg == 1) ? HD : KVXR;
        const uint4* s4 = (const uint4*)(sh + rowd * TSTR + hs * 64);
        uint4* d4 = (uint4*)(dstT + ((size_t)bh * rstr + d) * SEQ + s0 + hs * 64);
#pragma unroll
        for (int i = 0; i < 8; i++) d4[i] = s4[i];
    }
}

// ---------------- fused prep: pad embeddings + vT tail + qkv bias concat ----------------
#define PREP_PAD  (BS*KPAD)                // 20,971,520
#define PREP_VT   (BH*16*SEQ)              // 4,194,304
#define PREP_TOT  (PREP_PAD + PREP_VT + NLAY*QKVN)

__global__ void prep_all(const float* __restrict__ emb, __half* __restrict__ he,
                         __half* __restrict__ vT,
                         const float* __restrict__ bq, const float* __restrict__ bk,
                         const float* __restrict__ bv, float* __restrict__ bqkv)
{
    int i = blockIdx.x * 256 + threadIdx.x;
    if (i < PREP_PAD) {
        int r = i / KPAD, c = i - r * KPAD;
        he[i] = (c < F_IN) ? __float2half(emb[(size_t)r * F_IN + c]) : __half(0.f);
    } else if (i < PREP_PAD + PREP_VT) {
        int j = i - PREP_PAD;
        int bh = j / (16 * SEQ);
        int rem = j - bh * 16 * SEQ;
        int row = 64 + rem / SEQ;
        int s = rem % SEQ;
        vT[((size_t)bh * KVXR + row) * SEQ + s] = (row == 64) ? __half(1.f) : __half(0.f);
    } else if (i < PREP_TOT) {
        int j = i - PREP_PAD - PREP_VT;
        int l = j / QKVN, c = j - l * QKVN;
        float v;
        if (c < DM)           v = bq[l * DM + c];
        else if (c < 2 * DM)  v = bk[l * DM + c - DM];
        else                  v = bv[l * DM + c - 2 * DM];
        bqkv[j] = v;
    }
}

// ---------------- batched weight transpose ----------------
#define NTR 13
struct TrDesc { const float* in; __half* out; int K; int N; int KP; int tileStart; };
struct TrPack { TrDesc d[NTR]; };

__global__ void transpose_batch(TrPack p) {
    __shared__ float t[32][33];
    const int bt = blockIdx.x;
    int mi = 0;
#pragma unroll
    for (int i = 1; i < NTR; i++)
        if (bt >= p.d[i].tileStart) mi = i;
    const TrDesc de = p.d[mi];
    const int lt = bt - de.tileStart;
    const int ktiles = de.KP >> 5;
    const int k0 = (lt % ktiles) * 32;
    const int n0 = (lt / ktiles) * 32;
    const int x = threadIdx.x, y = threadIdx.y;
#pragma unroll
    for (int j = 0; j < 32; j += 8) {
        int kk = k0 + y + j;
        t[y + j][x] = (kk < de.K && n0 + x < de.N)
                      ? de.in[(size_t)kk * de.N + n0 + x] : 0.f;
    }
    __syncthreads();
#pragma unroll
    for (int j = 0; j < 32; j += 8)
        if (n0 + y + j < de.N)
            de.out[(size_t)(n0 + y + j) * de.KP + k0 + x] = __float2half(t[x][y + j]);
}

// ---------------- kv partials via mma: part[m,d] = sum_s vT80[m,s] kT[d,s] ----------------
__global__ __launch_bounds__(128) void kv_mma(
    const __half* __restrict__ kT, const __half* __restrict__ vT,
    float* __restrict__ kvpart)
{
    __shared__ __half smA[2][KVXR * 64];
    __shared__ __half smB[2][64 * 64];
    const uint32_t aBase0 = smem_u32(smA);
    const uint32_t bBase0 = smem_u32(smB);
    const int bh = blockIdx.x;
    const int chunk = blockIdx.y;
    const int tid = threadIdx.x;
    const int warp = tid >> 5;
    const int lane = tid & 31;
    const int g = lane >> 2, t = lane & 3;
    const int lrow = lane & 15, khalf = lane >> 4;
    const int s0 = chunk * KV_CH;

    const int ldr = tid >> 3;
    const int ldc = tid & 7;
    auto loadTile = [&](int it, int buf) {
        const int k0 = s0 + it * 64;
#pragma unroll
        for (int p = 0; p < 5; p++) {
            int row = p * 16 + ldr;
            uint32_t off = buf * (KVXR * 128) + row * 128 + ((ldc ^ (row & 7)) << 4);
            cp_async16(aBase0 + off, &vT[((size_t)bh * KVXR + row) * SEQ + k0 + ldc * 8]);
        }
#pragma unroll
        for (int p = 0; p < 4; p++) {
            int row = p * 16 + ldr;
            uint32_t off = buf * 8192 + row * 128 + ((ldc ^ (row & 7)) << 4);
            cp_async16(bBase0 + off, &kT[((size_t)bh * HD + row) * SEQ + k0 + ldc * 8]);
        }
    };

    float acc[5][2][4];
#pragma unroll
    for (int mt = 0; mt < 5; mt++)
#pragma unroll
        for (int j = 0; j < 2; j++)
#pragma unroll
            for (int i = 0; i < 4; i++) acc[mt][j][i] = 0.f;

    loadTile(0, 0);
    CP_COMMIT();

#pragma unroll 1
    for (int it = 0; it < KV_CH / 64; ++it) {
        const int buf = it & 1;
        CP_WAIT0();
        __syncthreads();
        if (it + 1 < KV_CH / 64) {
            loadTile(it + 1, buf ^ 1);
            CP_COMMIT();
        }
        const uint32_t Ab = aBase0 + buf * (KVXR * 128);
        const uint32_t Bb = bBase0 + buf * 8192;
#pragma unroll
        for (int ks = 0; ks < 4; ks++) {
            const int cIdx = 2 * ks + khalf;
            uint32_t a[5][4];
#pragma unroll
            for (int mt = 0; mt < 5; mt++) {
                int row = mt * 16 + lrow;
                ldmatrix_x4(a[mt], Ab + row * 128 + ((cIdx ^ (row & 7)) << 4));
            }
            uint32_t br[4];
            {
                int row = warp * 16 + lrow;
                ldmatrix_x4(br, Bb + row * 128 + ((cIdx ^ (row & 7)) << 4));
            }
#pragma unroll
            for (int mt = 0; mt < 5; mt++) {
                mma_f16(acc[mt][0], a[mt], br[0], br[2]);
                mma_f16(acc[mt][1], a[mt], br[1], br[3]);
            }
        }
    }

#pragma unroll
    for (int mt = 0; mt < 5; mt++)
#pragma unroll
        for (int j = 0; j < 2; j++)
#pragma unroll
            for (int sub = 0; sub < 2; sub++) {
                int m = mt * 16 + g + sub * 8;
                int d = warp * 16 + j * 8 + 2 * t;
                float2 o;
                o.x = acc[mt][j][sub * 2 + 0];
                o.y = acc[mt][j][sub * 2 + 1];
                *(float2*)&kvpart[(((size_t)chunk * BH + bh) * KVXR + m) * HD + d] = o;
            }
}

// ---------------- reduce partials -> kvx ----------------
__global__ __launch_bounds__(256) void reduce_kvx(
    const float* __restrict__ kvpart, __half* __restrict__ kvx)
{
    const int bh = blockIdx.x;
    for (int idx = threadIdx.x; idx < KVXR * HD; idx += 256) {
        float v = 0.f;
#pragma unroll
        for (int c = 0; c < NCHUNK; c++)
            v += kvpart[((size_t)c * BH + bh) * (KVXR * HD) + idx];
        kvx[(size_t)bh * (KVXR * HD) + idx] = __float2half(v);
    }
}

// ---------------- attention via mma: C[64,80] = q_tile @ kvx^T; z from col 64 ----------------
__global__ __launch_bounds__(128) void attn_mma(
    const __half* __restrict__ q, const __half* __restrict__ kvx,
    __half* __restrict__ out)
{
    __shared__ __half smA[64 * 64];
    __shared__ __half smB[KVXR * 64];
    const uint32_t aBase = smem_u32(smA);
    const uint32_t bBase = smem_u32(smB);
    const int bh = blockIdx.x;
    const int s0 = blockIdx.y * 64;
    const int b = bh >> 3, h = bh & 7;
    const int tid = threadIdx.x;
    const int warp = tid >> 5;
    const int lane = tid & 31;
    const int g = lane >> 2, t = lane & 3;
    const int lrow = lane & 15, khalf = lane >> 4;

    {
        const int ldr = tid >> 3, ldc = tid & 7;
#pragma unroll
        for (int p = 0; p < 4; p++) {
            int row = p * 16 + ldr;
            uint32_t dst = aBase + row * 128 + ((ldc ^ (row & 7)) << 4);
            cp_async16(dst, &q[(size_t)(b * SEQ + s0 + row) * DM + h * HD + ldc * 8]);
        }
#pragma unroll
        for (int p = 0; p < 5; p++) {
            int row = p * 16 + ldr;
            uint32_t dst = bBase + row * 128 + ((ldc ^ (row & 7)) << 4);
            cp_async16(dst, &kvx[((size_t)bh * KVXR + row) * HD + ldc * 8]);
        }
        CP_COMMIT();
        CP_WAIT0();
        __syncthreads();
    }

    float acc[10][4];
#pragma unroll
    for (int nt = 0; nt < 10; nt++)
#pragma unroll
        for (int i = 0; i < 4; i++) acc[nt][i] = 0.f;

#pragma unroll
    for (int ks = 0; ks < 4; ks++) {
        const int cIdx = 2 * ks + khalf;
        uint32_t a[4];
        {
            int row = warp * 16 + lrow;
            ldmatrix_x4(a, aBase + row * 128 + ((cIdx ^ (row & 7)) << 4));
        }
#pragma unroll
        for (int j = 0; j < 5; j++) {
            uint32_t br[4];
            int row = j * 16 + lrow;
            ldmatrix_x4(br, bBase + row * 128 + ((cIdx ^ (row & 7)) << 4));
            mma_f16(acc[2 * j],     a, br[0], br[2]);
            mma_f16(acc[2 * j + 1], a, br[1], br[3]);
        }
    }

    float d0 = __shfl_sync(0xffffffffu, acc[8][0], lane & 28);
    float d1 = __shfl_sync(0xffffffffu, acc[8][2], lane & 28);
    float z0 = 1.f / (d0 + EPS_ATTN);
    float z1 = 1.f / (d1 + EPS_ATTN);

    const int r0 = s0 + warp * 16 + g;
#pragma unroll
    for (int nt = 0; nt < 8; nt++) {
        int c = nt * 8 + 2 * t;
        *(__half2*)&out[(size_t)(b * SEQ + r0) * DM + h * HD + c] =
            __floats2half2_rn(acc[nt][0] * z0, acc[nt][1] * z0);
        *(__half2*)&out[(size_t)(b * SEQ + r0 + 8) * DM + h * HD + c] =
            __floats2half2_rn(acc[nt][2] * z1, acc[nt][3] * z1);
    }
}

// ---------------- block reduce helper ----------------
__device__ __forceinline__ float bsum128(float v, float* sm) {
#pragma unroll
    for (int o = 16; o > 0; o >>= 1) v += __shfl_down_sync(0xffffffffu, v, o);
    int w = threadIdx.x >> 5;
    if ((threadIdx.x & 31) == 0) sm[w] = v;
    __syncthreads();
    float r = sm[0] + sm[1] + sm[2] + sm[3];
    __syncthreads();
    return r;
}

// ---------------- layernorm: fp16 in -> fp16 out ----------------
__global__ __launch_bounds__(128) void ln_kernel(
    const __half* __restrict__ in, const float* __restrict__ g,
    const float* __restrict__ b, __half* __restrict__ hout)
{
    __shared__ float sm[4];
    const int row = blockIdx.x;
    const int tid = threadIdx.x;
    uint2 raw = ((const uint2*)(in + (size_t)row * DM))[tid];
    float2 f0 = __half22float2(*(__half2*)&raw.x);
    float2 f1 = __half22float2(*(__half2*)&raw.y);
    float s  = f0.x + f0.y + f1.x + f1.y;
    float sq = f0.x * f0.x + f0.y * f0.y + f1.x * f1.x + f1.y * f1.y;
    s  = bsum128(s, sm);
    sq = bsum128(sq, sm);
    float mu = s * (1.f / DM);
    float var = sq * (1.f / DM) - mu * mu;
    float rstd = rsqrtf(var + EPS_LN);
    float4 gg = ((const float4*)g)[tid];
    float4 bb = ((const float4*)b)[tid];
    float ox = (f0.x - mu) * rstd * gg.x + bb.x;
    float oy = (f0.y - mu) * rstd * gg.y + bb.y;
    float oz = (f1.x - mu) * rstd * gg.z + bb.z;
    float ow = (f1.y - mu) * rstd * gg.w + bb.w;
    uint2 pk;
    *(__half2*)&pk.x = __floats2half2_rn(ox, oy);
    *(__half2*)&pk.y = __floats2half2_rn(oz, ow);
    ((uint2*)(hout + (size_t)row * DM))[tid] = pk;
}

// ---------------- fused final LN + out proj (fp16 in) ----------------
__global__ __launch_bounds__(128) void final_kernel(
    const __half* __restrict__ in, const float* __restrict__ g,
    const float* __restrict__ b, const float* __restrict__ w,
    const float* __restrict__ bout, float* __restrict__ out)
{
    __shared__ float sm[4];
    const int row = blockIdx.x;
    const int tid = threadIdx.x;
    uint2 raw = ((const uint2*)(in + (size_t)row * DM))[tid];
    float2 f0 = __half22float2(*(__half2*)&raw.x);
    float2 f1 = __half22float2(*(__half2*)&raw.y);
    float s  = f0.x + f0.y + f1.x + f1.y;
    float sq = f0.x * f0.x + f0.y * f0.y + f1.x * f1.x + f1.y * f1.y;
    s  = bsum128(s, sm);
    sq = bsum128(sq, sm);
    float mu = s * (1.f / DM);
    float var = sq * (1.f / DM) - mu * mu;
    float rstd = rsqrtf(var + EPS_LN);
    float4 gg = ((const float4*)g)[tid];
    float4 bb = ((const float4*)b)[tid];
    float4 ww = ((const float4*)w)[tid];
    float acc = ((f0.x - mu) * rstd * gg.x + bb.x) * ww.x
              + ((f0.y - mu) * rstd * gg.y + bb.y) * ww.y
              + ((f1.x - mu) * rstd * gg.z + bb.z) * ww.z
              + ((f1.y - mu) * rstd * gg.w + bb.w) * ww.w;
    acc = bsum128(acc, sm);
    if (tid == 0) out[row] = acc + bout[0];
}

extern "C" void kernel_launch(void* const* d_in, const int* in_sizes, int n_in,
                              void* d_out, int out_size)
{
    const float* emb   = (const float*)d_in[0];
    const float* W0    = (const float*)d_in[1];
    const float* b0    = (const float*)d_in[2];
    const float* Wq    = (const float*)d_in[3];
    const float* bq    = (const float*)d_in[4];
    const float* Wk    = (const float*)d_in[5];
    const float* bk    = (const float*)d_in[6];
    const float* Wv    = (const float*)d_in[7];
    const float* bv    = (const float*)d_in[8];
    const float* Wo    = (const float*)d_in[9];
    const float* bo    = (const float*)d_in[10];
    const float* ln1s  = (const float*)d_in[11];
    const float* ln1b  = (const float*)d_in[12];
    const float* W1    = (const float*)d_in[13];
    const float* b1    = (const float*)d_in[14];
    const float* W2    = (const float*)d_in[15];
    const float* b2    = (const float*)d_in[16];
    const float* ln2s  = (const float*)d_in[17];
    const float* ln2b  = (const float*)d_in[18];
    const float* lnfs  = (const float*)d_in[19];
    const float* lnfb  = (const float*)d_in[20];
    const float* Wout  = (const float*)d_in[21];
    const float* bout  = (const float*)d_in[22];
    float* out = (float*)d_out;

    auto gemm_in   = gemm_t<10, DM,   0, 0, 1>;
    auto gemm_qkv  = gemm_t<8,  QKVN, 3, 0, 3>;
    auto gemm_wo   = gemm_t<8,  DM,   0, 2, 1>;
    auto gemm_ffn1 = gemm_t<8,  FF,   2, 0, 1>;
    auto gemm_ffn2 = gemm_t<16, DM,   0, 2, 1>;
    cudaFuncSetAttribute(gemm_in,   cudaFuncAttributeMaxDynamicSharedMemorySize, GEMM_SMEM);
    cudaFuncSetAttribute(gemm_qkv,  cudaFuncAttributeMaxDynamicSharedMemorySize, GEMM_SMEM);
    cudaFuncSetAttribute(gemm_wo,   cudaFuncAttributeMaxDynamicSharedMemorySize, GEMM_SMEM);
    cudaFuncSetAttribute(gemm_ffn1, cudaFuncAttributeMaxDynamicSharedMemorySize, GEMM_SMEM);
    cudaFuncSetAttribute(gemm_ffn2, cudaFuncAttributeMaxDynamicSharedMemorySize, GEMM_SMEM);

    __half *he, *hx, *hy, *hq, *ht, *hh, *kT, *vT, *kvx;
    __half *w0t, *wqkvt, *wot, *w1t, *w2t;
    float *pkvp, *bqkv;
    cudaGetSymbolAddress((void**)&he,  g_he);
    cudaGetSymbolAddress((void**)&hx,  g_hx);
    cudaGetSymbolAddress((void**)&hy,  g_hy);
    cudaGetSymbolAddress((void**)&hq,  g_hq);
    cudaGetSymbolAddress((void**)&ht,  g_ht);
    cudaGetSymbolAddress((void**)&hh,  g_hh);
    cudaGetSymbolAddress((void**)&kT,  g_kT);
    cudaGetSymbolAddress((void**)&vT,  g_vT);
    cudaGetSymbolAddress((void**)&kvx, g_kvx);
    cudaGetSymbolAddress((void**)&pkvp, g_kvpart);
    cudaGetSymbolAddress((void**)&w0t, g_w0t);
    cudaGetSymbolAddress((void**)&wqkvt, g_wqkvt);
    cudaGetSymbolAddress((void**)&wot, g_wot);
    cudaGetSymbolAddress((void**)&w1t, g_w1t);
    cudaGetSymbolAddress((void**)&w2t, g_w2t);
    cudaGetSymbolAddress((void**)&bqkv, g_bqkv);

    // ---- prep (single fused launch + batched transpose) ----
    prep_all<<<(PREP_TOT + 255) / 256, 256>>>(emb, he, vT, bq, bk, bv, bqkv);

    TrPack pack;
    int tileOff = 0;
    auto addTr = [&](int idx, const float* in, __half* outp, int K, int N, int KP) {
        pack.d[idx].in = in; pack.d[idx].out = outp;
        pack.d[idx].K = K; pack.d[idx].N = N; pack.d[idx].KP = KP;
        pack.d[idx].tileStart = tileOff;
        tileOff += (KP / 32) * ((N + 31) / 32);
    };
    int di = 0;
    addTr(di++, W0, w0t, F_IN, DM, KPAD);
    for (int l = 0; l < NLAY; l++) {
        __half* wl = wqkvt + (size_t)l * QKVN * DM;
        addTr(di++, Wq + (size_t)l * DM * DM, wl,                        DM, DM, DM);
        addTr(di++, Wk + (size_t)l * DM * DM, wl + (size_t)DM * DM,      DM, DM, DM);
        addTr(di++, Wv + (size_t)l * DM * DM, wl + (size_t)2 * DM * DM,  DM, DM, DM);
        addTr(di++, Wo + (size_t)l * DM * DM, wot + (size_t)l * DM * DM, DM, DM, DM);
        addTr(di++, W1 + (size_t)l * DM * FF, w1t + (size_t)l * DM * FF, DM, FF, DM);
        addTr(di++, W2 + (size_t)l * FF * DM, w2t + (size_t)l * FF * DM, FF, DM, FF);
    }
    transpose_batch<<<tileOff, dim3(32, 8)>>>(pack);

    // ---- input projection -> hx fp16 ----
    gemm_in<<<dim3(DM / GBN, BS / GBM), 256, GEMM_SMEM>>>(
        he, w0t, b0, nullptr, hx, nullptr, nullptr);

    for (int l = 0; l < NLAY; l++) {
        const __half* wqkv_l = wqkvt + (size_t)l * QKVN * DM;
        const __half* wot_l  = wot + (size_t)l * DM * DM;
        const __half* w1t_l  = w1t + (size_t)l * DM * FF;
        const __half* w2t_l  = w2t + (size_t)l * FF * DM;
        const float* bqkv_l = bqkv + (size_t)l * QKVN;
        const float* bo_l = bo + (size_t)l * DM;
        const float* b1_l = b1 + (size_t)l * FF;
        const float* b2_l = b2 + (size_t)l * DM;

        gemm_qkv<<<dim3(QKVN / GBN, BS / GBM), 256, GEMM_SMEM>>>(
            hx, wqkv_l, bqkv_l, nullptr, hq, kT, vT);

        kv_mma<<<dim3(BH, NCHUNK), 128>>>(kT, vT, pkvp);
        reduce_kvx<<<BH, 256>>>(pkvp, kvx);
        attn_mma<<<dim3(BH, SEQ / 64), 128>>>(hq, kvx, ht);

        gemm_wo<<<dim3(DM / GBN, BS / GBM), 256, GEMM_SMEM>>>(
            ht, wot_l, bo_l, hx, hy, nullptr, nullptr);
        ln_kernel<<<BS, 128>>>(hy, ln1s + (size_t)l * DM, ln1b + (size_t)l * DM, hx);

        gemm_ffn1<<<dim3(FF / GBN, BS / GBM), 256, GEMM_SMEM>>>(
            hx, w1t_l, b1_l, nullptr, hh, nullptr, nullptr);
        gemm_ffn2<<<dim3(DM / GBN, BS / GBM), 256, GEMM_SMEM>>>(
            hh, w2t_l, b2_l, hx, hy, nullptr, nullptr);
        ln_kernel<<<BS, 128>>>(hy, ln2s + (size_t)l * DM, ln2b + (size_t)l * DM, hx);
    }

    final_kernel<<<BS, 128>>>(hx, lnfs, lnfb, Wout, bout, out);
}

// round 17
// speedup vs baseline: 1.0658x; 1.0459x over previous
#include <cuda_runtime.h>
#include <cuda_fp16.h>
#include <math.h>
#include <stdint.h>

// ---------------- problem constants ----------------
#define BATCH 8
#define SEQ   4096
#define F_IN  586
#define KPAD  640
#define DM    512
#define NH    8
#define HD    64
#define FF    1024
#define NLAY  2
#define BS    (BATCH*SEQ)
#define BH    (BATCH*NH)
#define QKVN  (3*DM)
#define EPS_ATTN 1e-6f
#define EPS_LN   1e-5f
#define NCHUNK 8
#define KV_CH  (SEQ/NCHUNK)    // 512
#define KVXR   80              // kv rows: 64 kvT + 1 ks + 15 pad
#define TSTR   136             // staging stride in halves (128 + 8 pad)

// ---------------- scratch ----------------
__device__ __half g_he[BS*KPAD];
__device__ __half g_hx[BS*DM];
__device__ __half g_hy[BS*DM];
__device__ __half g_hq[BS*DM];
__device__ __half g_ht[BS*DM];
__device__ __half g_hh[BS*FF];
__device__ __half g_kT[(size_t)BH*HD*SEQ];
__device__ __half g_vT[(size_t)BH*KVXR*SEQ];
__device__ float  g_kvpart[NCHUNK*BH*KVXR*HD];
__device__ __half g_kvx[BH*KVXR*HD];
__device__ __half g_w0t [DM*KPAD];
__device__ __half g_wqkvt[NLAY*QKVN*DM];
__device__ __half g_wot [NLAY*DM*DM];
__device__ __half g_w1t [NLAY*FF*DM];
__device__ __half g_w2t [NLAY*DM*FF];
__device__ float  g_bqkv[NLAY*QKVN];

// ---------------- helpers ----------------
__device__ __forceinline__ uint32_t smem_u32(const void* p) {
    uint32_t a;
    asm("{ .reg .u64 t; cvta.to.shared.u64 t, %1; cvt.u32.u64 %0, t; }" : "=r"(a) : "l"(p));
    return a;
}
__device__ __forceinline__ void cp_async16(uint32_t dst, const void* src) {
    asm volatile("cp.async.cg.shared.global [%0], [%1], 16;"
                 :: "r"(dst), "l"(src) : "memory");
}
#define CP_COMMIT() asm volatile("cp.async.commit_group;" ::: "memory")
#define CP_WAIT0()  asm volatile("cp.async.wait_group 0;" ::: "memory")

__device__ __forceinline__ void ldmatrix_x4(uint32_t* r, uint32_t addr) {
    asm volatile("ldmatrix.sync.aligned.m8n8.x4.shared.b16 {%0,%1,%2,%3}, [%4];"
                 : "=r"(r[0]), "=r"(r[1]), "=r"(r[2]), "=r"(r[3]) : "r"(addr));
}
__device__ __forceinline__ void mma_f16(float* c, const uint32_t* a, uint32_t b0, uint32_t b1) {
    asm volatile(
        "mma.sync.aligned.m16n8k16.row.col.f32.f16.f16.f32 "
        "{%0,%1,%2,%3}, {%4,%5,%6,%7}, {%8,%9}, {%0,%1,%2,%3};"
        : "+f"(c[0]), "+f"(c[1]), "+f"(c[2]), "+f"(c[3])
        : "r"(a[0]), "r"(a[1]), "r"(a[2]), "r"(a[3]), "r"(b0), "r"(b1));
}

// ---------------- templated fp16 tensor-core GEMM ----------------
// RES: 0 none, 2 = fp16 residual
// OM:  1 = fp16 out (Ch), 3 = qkv split (q -> Ch; k,v -> head-transposed Ch2/Ch3)
#define GBM 128
#define GBN 128
#define TILE_B 16384
#define GEMM_SMEM (4*TILE_B)

template<int KITERS, int N, int ACT, int RES, int OM>
__global__ __launch_bounds__(256) void gemm_t(
    const __half* __restrict__ A, const __half* __restrict__ BT,
    const float* __restrict__ bias, const __half* __restrict__ resh,
    __half* __restrict__ Ch, __half* __restrict__ Ch2, __half* __restrict__ Ch3)
{
    constexpr int K = KITERS * 64;
    extern __shared__ char smraw[];
    const uint32_t smBase = smem_u32(smraw);
    const int tid  = threadIdx.x;
    const int warp = tid >> 5;
    const int lane = tid & 31;
    const int g = lane >> 2;
    const int t = lane & 3;
    const int warpM = warp & 3;
    const int warpN = warp >> 2;
    const int rowBase = blockIdx.y * GBM;
    const int colBase = blockIdx.x * GBN;

    const int ldr = tid >> 3;
    const int ldc = tid & 7;
    auto loadTile = [&](int it, int buf) {
        const int k0 = it * 64;
#pragma unroll
        for (int p = 0; p < 4; p++) {
            int row = p * 32 + ldr;
            uint32_t dst = smBase + buf * TILE_B + row * 128 + ((ldc ^ (row & 7)) << 4);
            cp_async16(dst, &A[(size_t)(rowBase + row) * K + k0 + ldc * 8]);
        }
#pragma unroll
        for (int p = 0; p < 4; p++) {
            int row = p * 32 + ldr;
            uint32_t dst = smBase + 2 * TILE_B + buf * TILE_B + row * 128 + ((ldc ^ (row & 7)) << 4);
            cp_async16(dst, &BT[(size_t)(colBase + row) * K + k0 + ldc * 8]);
        }
    };

    float acc[2][8][4];
#pragma unroll
    for (int mt = 0; mt < 2; mt++)
#pragma unroll
        for (int nt = 0; nt < 8; nt++)
#pragma unroll
            for (int i = 0; i < 4; i++) acc[mt][nt][i] = 0.f;

    loadTile(0, 0);
    CP_COMMIT();

    const int lrow = lane & 15;
    const int khalf = lane >> 4;

#pragma unroll 1
    for (int it = 0; it < KITERS; ++it) {
        const int buf = it & 1;
        CP_WAIT0();
        __syncthreads();
        if (it + 1 < KITERS) {
            loadTile(it + 1, buf ^ 1);
            CP_COMMIT();
        }
        const uint32_t Abase = smBase + buf * TILE_B;
        const uint32_t Bbase = smBase + 2 * TILE_B + buf * TILE_B;
#pragma unroll
        for (int ks = 0; ks < 4; ks++) {
            const int cIdx = 2 * ks + khalf;
            uint32_t a[2][4];
#pragma unroll
            for (int mt = 0; mt < 2; mt++) {
                int row = warpM * 32 + mt * 16 + lrow;
                ldmatrix_x4(a[mt], Abase + row * 128 + ((cIdx ^ (row & 7)) << 4));
            }
            uint32_t br[4][4];
#pragma unroll
            for (int j = 0; j < 4; j++) {
                int row = warpN * 64 + j * 16 + lrow;
                ldmatrix_x4(br[j], Bbase + row * 128 + ((cIdx ^ (row & 7)) << 4));
            }
#pragma unroll
            for (int mt = 0; mt < 2; mt++)
#pragma unroll
                for (int j = 0; j < 4; j++) {
                    mma_f16(acc[mt][2 * j],     a[mt], br[j][0], br[j][2]);
                    mma_f16(acc[mt][2 * j + 1], a[mt], br[j][1], br[j][3]);
                }
        }
    }

    // ---- epilogue ----
    const bool stage = (OM == 3) && (colBase >= 512);
    __half* sh = (__half*)smraw;
    if (stage) __syncthreads();

#pragma unroll
    for (int mt = 0; mt < 2; mt++) {
#pragma unroll
        for (int sub = 0; sub < 2; sub++) {
            const int rl = warpM * 32 + mt * 16 + g + sub * 8;
            const int r = rowBase + rl;
#pragma unroll
            for (int nt = 0; nt < 8; nt++) {
                const int cl = warpN * 64 + nt * 8 + 2 * t;
                const int c = colBase + cl;
                float2 o;
                o.x = acc[mt][nt][sub * 2 + 0];
                o.y = acc[mt][nt][sub * 2 + 1];
                float2 bi = *(const float2*)&bias[c];
                o.x += bi.x; o.y += bi.y;
                if (RES == 2) {
                    float2 rr = __half22float2(*(const __half2*)&resh[(size_t)r * N + c]);
                    o.x += rr.x; o.y += rr.y;
                }
                if (ACT == 1 || (ACT == 3 && c < 2 * DM)) {
                    o.x = (o.x > 0.f) ? (o.x + 1.f) : __expf(o.x);
                    o.y = (o.y > 0.f) ? (o.y + 1.f) : __expf(o.y);
                } else if (ACT == 2) {
                    o.x = fmaxf(o.x, 0.f);
                    o.y = fmaxf(o.y, 0.f);
                }
                if (OM == 3) {
                    if (!stage) {
                        *(__half2*)&Ch[(size_t)r * DM + c] = __floats2half2_rn(o.x, o.y);
                    } else {
                        sh[cl * TSTR + rl]       = __float2half(o.x);
                        sh[(cl + 1) * TSTR + rl] = __float2half(o.y);
                    }
                } else {
                    *(__half2*)&Ch[(size_t)r * N + c] = __floats2half2_rn(o.x, o.y);
                }
            }
        }
    }

    if (stage) {
        __syncthreads();
        const int seg = colBase >> 9;          // 1 = k, 2 = v
        const int rowd = tid >> 1;
        const int hs = tid & 1;
        const int hloc = rowd >> 6, d = rowd & 63;
        const int b = rowBase >> 12;
        const int s0 = rowBase & (SEQ - 1);
        const int hbase = (colBase & 511) >> 6;
        const int bh = b * NH + hbase + hloc;
        __half* dstT = (seg == 1) ? Ch2 : Ch3;
        const size_t rstr = (seg == 1) ? HD : KVXR;
        const uint4* s4 = (const uint4*)(sh + rowd * TSTR + hs * 64);
        uint4* d4 = (uint4*)(dstT + ((size_t)bh * rstr + d) * SEQ + s0 + hs * 64);
#pragma unroll
        for (int i = 0; i < 8; i++) d4[i] = s4[i];
    }
}

// ---------------- fused prep: pad embeddings + vT tail + qkv bias concat ----------------
#define PREP_PAD  (BS*KPAD)
#define PREP_VT   (BH*16*SEQ)
#define PREP_TOT  (PREP_PAD + PREP_VT + NLAY*QKVN)

__global__ void prep_all(const float* __restrict__ emb, __half* __restrict__ he,
                         __half* __restrict__ vT,
                         const float* __restrict__ bq, const float* __restrict__ bk,
                         const float* __restrict__ bv, float* __restrict__ bqkv)
{
    int i = blockIdx.x * 256 + threadIdx.x;
    if (i < PREP_PAD) {
        int r = i / KPAD, c = i - r * KPAD;
        he[i] = (c < F_IN) ? __float2half(emb[(size_t)r * F_IN + c]) : __half(0.f);
    } else if (i < PREP_PAD + PREP_VT) {
        int j = i - PREP_PAD;
        int bh = j / (16 * SEQ);
        int rem = j - bh * 16 * SEQ;
        int row = 64 + rem / SEQ;
        int s = rem % SEQ;
        vT[((size_t)bh * KVXR + row) * SEQ + s] = (row == 64) ? __half(1.f) : __half(0.f);
    } else if (i < PREP_TOT) {
        int j = i - PREP_PAD - PREP_VT;
        int l = j / QKVN, c = j - l * QKVN;
        float v;
        if (c < DM)           v = bq[l * DM + c];
        else if (c < 2 * DM)  v = bk[l * DM + c - DM];
        else                  v = bv[l * DM + c - 2 * DM];
        bqkv[j] = v;
    }
}

// ---------------- batched weight transpose ----------------
#define NTR 13
struct TrDesc { const float* in; __half* out; int K; int N; int KP; int tileStart; };
struct TrPack { TrDesc d[NTR]; };

__global__ void transpose_batch(TrPack p) {
    __shared__ float t[32][33];
    const int bt = blockIdx.x;
    int mi = 0;
#pragma unroll
    for (int i = 1; i < NTR; i++)
        if (bt >= p.d[i].tileStart) mi = i;
    const TrDesc de = p.d[mi];
    const int lt = bt - de.tileStart;
    const int ktiles = de.KP >> 5;
    const int k0 = (lt % ktiles) * 32;
    const int n0 = (lt / ktiles) * 32;
    const int x = threadIdx.x, y = threadIdx.y;
#pragma unroll
    for (int j = 0; j < 32; j += 8) {
        int kk = k0 + y + j;
        t[y + j][x] = (kk < de.K && n0 + x < de.N)
                      ? de.in[(size_t)kk * de.N + n0 + x] : 0.f;
    }
    __syncthreads();
#pragma unroll
    for (int j = 0; j < 32; j += 8)
        if (n0 + y + j < de.N)
            de.out[(size_t)(n0 + y + j) * de.KP + k0 + x] = __float2half(t[x][y + j]);
}

// ---------------- kv partials via mma: part[m,d] = sum_s vT80[m,s] kT[d,s] ----------------
__global__ __launch_bounds__(128) void kv_mma(
    const __half* __restrict__ kT, const __half* __restrict__ vT,
    float* __restrict__ kvpart)
{
    __shared__ __half smA[2][KVXR * 64];
    __shared__ __half smB[2][64 * 64];
    const uint32_t aBase0 = smem_u32(smA);
    const uint32_t bBase0 = smem_u32(smB);
    const int bh = blockIdx.x;
    const int chunk = blockIdx.y;
    const int tid = threadIdx.x;
    const int warp = tid >> 5;
    const int lane = tid & 31;
    const int g = lane >> 2, t = lane & 3;
    const int lrow = lane & 15, khalf = lane >> 4;
    const int s0 = chunk * KV_CH;

    const int ldr = tid >> 3;
    const int ldc = tid & 7;
    auto loadTile = [&](int it, int buf) {
        const int k0 = s0 + it * 64;
#pragma unroll
        for (int p = 0; p < 5; p++) {
            int row = p * 16 + ldr;
            uint32_t off = buf * (KVXR * 128) + row * 128 + ((ldc ^ (row & 7)) << 4);
            cp_async16(aBase0 + off, &vT[((size_t)bh * KVXR + row) * SEQ + k0 + ldc * 8]);
        }
#pragma unroll
        for (int p = 0; p < 4; p++) {
            int row = p * 16 + ldr;
            uint32_t off = buf * 8192 + row * 128 + ((ldc ^ (row & 7)) << 4);
            cp_async16(bBase0 + off, &kT[((size_t)bh * HD + row) * SEQ + k0 + ldc * 8]);
        }
    };

    float acc[5][2][4];
#pragma unroll
    for (int mt = 0; mt < 5; mt++)
#pragma unroll
        for (int j = 0; j < 2; j++)
#pragma unroll
            for (int i = 0; i < 4; i++) acc[mt][j][i] = 0.f;

    loadTile(0, 0);
    CP_COMMIT();

#pragma unroll 1
    for (int it = 0; it < KV_CH / 64; ++it) {
        const int buf = it & 1;
        CP_WAIT0();
        __syncthreads();
        if (it + 1 < KV_CH / 64) {
            loadTile(it + 1, buf ^ 1);
            CP_COMMIT();
        }
        const uint32_t Ab = aBase0 + buf * (KVXR * 128);
        const uint32_t Bb = bBase0 + buf * 8192;
#pragma unroll
        for (int ks = 0; ks < 4; ks++) {
            const int cIdx = 2 * ks + khalf;
            uint32_t a[5][4];
#pragma unroll
            for (int mt = 0; mt < 5; mt++) {
                int row = mt * 16 + lrow;
                ldmatrix_x4(a[mt], Ab + row * 128 + ((cIdx ^ (row & 7)) << 4));
            }
            uint32_t br[4];
            {
                int row = warp * 16 + lrow;
                ldmatrix_x4(br, Bb + row * 128 + ((cIdx ^ (row & 7)) << 4));
            }
#pragma unroll
            for (int mt = 0; mt < 5; mt++) {
                mma_f16(acc[mt][0], a[mt], br[0], br[2]);
                mma_f16(acc[mt][1], a[mt], br[1], br[3]);
            }
        }
    }

#pragma unroll
    for (int mt = 0; mt < 5; mt++)
#pragma unroll
        for (int j = 0; j < 2; j++)
#pragma unroll
            for (int sub = 0; sub < 2; sub++) {
                int m = mt * 16 + g + sub * 8;
                int d = warp * 16 + j * 8 + 2 * t;
                float2 o;
                o.x = acc[mt][j][sub * 2 + 0];
                o.y = acc[mt][j][sub * 2 + 1];
                *(float2*)&kvpart[(((size_t)chunk * BH + bh) * KVXR + m) * HD + d] = o;
            }
}

// ---------------- reduce partials -> kvx ----------------
__global__ __launch_bounds__(256) void reduce_kvx(
    const float* __restrict__ kvpart, __half* __restrict__ kvx)
{
    const int bh = blockIdx.x;
    for (int idx = threadIdx.x; idx < KVXR * HD; idx += 256) {
        float v = 0.f;
#pragma unroll
        for (int c = 0; c < NCHUNK; c++)
            v += kvpart[((size_t)c * BH + bh) * (KVXR * HD) + idx];
        kvx[(size_t)bh * (KVXR * HD) + idx] = __float2half(v);
    }
}

// ---------------- attention via mma: C[64,80] = q_tile @ kvx^T; z from col 64 ----------------
__global__ __launch_bounds__(128) void attn_mma(
    const __half* __restrict__ q, const __half* __restrict__ kvx,
    __half* __restrict__ out)
{
    __shared__ __half smA[64 * 64];
    __shared__ __half smB[KVXR * 64];
    const uint32_t aBase = smem_u32(smA);
    const uint32_t bBase = smem_u32(smB);
    const int bh = blockIdx.x;
    const int s0 = blockIdx.y * 64;
    const int b = bh >> 3, h = bh & 7;
    const int tid = threadIdx.x;
    const int warp = tid >> 5;
    const int lane = tid & 31;
    const int g = lane >> 2, t = lane & 3;
    const int lrow = lane & 15, khalf = lane >> 4;

    {
        const int ldr = tid >> 3, ldc = tid & 7;
#pragma unroll
        for (int p = 0; p < 4; p++) {
            int row = p * 16 + ldr;
            uint32_t dst = aBase + row * 128 + ((ldc ^ (row & 7)) << 4);
            cp_async16(dst, &q[(size_t)(b * SEQ + s0 + row) * DM + h * HD + ldc * 8]);
        }
#pragma unroll
        for (int p = 0; p < 5; p++) {
            int row = p * 16 + ldr;
            uint32_t dst = bBase + row * 128 + ((ldc ^ (row & 7)) << 4);
            cp_async16(dst, &kvx[((size_t)bh * KVXR + row) * HD + ldc * 8]);
        }
        CP_COMMIT();
        CP_WAIT0();
        __syncthreads();
    }

    float acc[10][4];
#pragma unroll
    for (int nt = 0; nt < 10; nt++)
#pragma unroll
        for (int i = 0; i < 4; i++) acc[nt][i] = 0.f;

#pragma unroll
    for (int ks = 0; ks < 4; ks++) {
        const int cIdx = 2 * ks + khalf;
        uint32_t a[4];
        {
            int row = warp * 16 + lrow;
            ldmatrix_x4(a, aBase + row * 128 + ((cIdx ^ (row & 7)) << 4));
        }
#pragma unroll
        for (int j = 0; j < 5; j++) {
            uint32_t br[4];
            int row = j * 16 + lrow;
            ldmatrix_x4(br, bBase + row * 128 + ((cIdx ^ (row & 7)) << 4));
            mma_f16(acc[2 * j],     a, br[0], br[2]);
            mma_f16(acc[2 * j + 1], a, br[1], br[3]);
        }
    }

    float d0 = __shfl_sync(0xffffffffu, acc[8][0], lane & 28);
    float d1 = __shfl_sync(0xffffffffu, acc[8][2], lane & 28);
    float z0 = 1.f / (d0 + EPS_ATTN);
    float z1 = 1.f / (d1 + EPS_ATTN);

    const int r0 = s0 + warp * 16 + g;
#pragma unroll
    for (int nt = 0; nt < 8; nt++) {
        int c = nt * 8 + 2 * t;
        *(__half2*)&out[(size_t)(b * SEQ + r0) * DM + h * HD + c] =
            __floats2half2_rn(acc[nt][0] * z0, acc[nt][1] * z0);
        *(__half2*)&out[(size_t)(b * SEQ + r0 + 8) * DM + h * HD + c] =
            __floats2half2_rn(acc[nt][2] * z1, acc[nt][3] * z1);
    }
}

// ---------------- warp-per-row layernorm: fp16 in -> fp16 out ----------------
__global__ __launch_bounds__(256) void ln_warp(
    const __half* __restrict__ in, const float* __restrict__ g,
    const float* __restrict__ b, __half* __restrict__ hout)
{
    const int warp = threadIdx.x >> 5, lane = threadIdx.x & 31;
    const int row = blockIdx.x * 8 + warp;
    const uint4* src = (const uint4*)(in + (size_t)row * DM);
    uint4 v0 = src[lane];
    uint4 v1 = src[lane + 32];
    const __half2* h0 = (const __half2*)&v0;
    const __half2* h1 = (const __half2*)&v1;
    float f[16];
    float s = 0.f, sq = 0.f;
#pragma unroll
    for (int i = 0; i < 4; i++) {
        float2 a = __half22float2(h0[i]);
        float2 c = __half22float2(h1[i]);
        f[2 * i] = a.x; f[2 * i + 1] = a.y;
        f[8 + 2 * i] = c.x; f[8 + 2 * i + 1] = c.y;
        s += a.x + a.y + c.x + c.y;
        sq += a.x * a.x + a.y * a.y + c.x * c.x + c.y * c.y;
    }
#pragma unroll
    for (int o = 16; o > 0; o >>= 1) {
        s  += __shfl_xor_sync(0xffffffffu, s, o);
        sq += __shfl_xor_sync(0xffffffffu, sq, o);
    }
    float mu = s * (1.f / DM);
    float rstd = rsqrtf(sq * (1.f / DM) - mu * mu + EPS_LN);
    const float4* g4 = (const float4*)g;
    const float4* b4 = (const float4*)b;
    uint4 o0, o1;
    __half2* p0 = (__half2*)&o0;
    __half2* p1 = (__half2*)&o1;
#pragma unroll
    for (int i = 0; i < 2; i++) {
        float4 gv = g4[lane * 2 + i];
        float4 bv = b4[lane * 2 + i];
        p0[2 * i]     = __floats2half2_rn((f[4 * i] - mu) * rstd * gv.x + bv.x,
                                          (f[4 * i + 1] - mu) * rstd * gv.y + bv.y);
        p0[2 * i + 1] = __floats2half2_rn((f[4 * i + 2] - mu) * rstd * gv.z + bv.z,
                                          (f[4 * i + 3] - mu) * rstd * gv.w + bv.w);
        float4 gw = g4[lane * 2 + 64 + i];
        float4 bw = b4[lane * 2 + 64 + i];
        p1[2 * i]     = __floats2half2_rn((f[8 + 4 * i] - mu) * rstd * gw.x + bw.x,
                                          (f[8 + 4 * i + 1] - mu) * rstd * gw.y + bw.y);
        p1[2 * i + 1] = __floats2half2_rn((f[8 + 4 * i + 2] - mu) * rstd * gw.z + bw.z,
                                          (f[8 + 4 * i + 3] - mu) * rstd * gw.w + bw.w);
    }
    uint4* dst = (uint4*)(hout + (size_t)row * DM);
    dst[lane] = o0;
    dst[lane + 32] = o1;
}

// ---------------- warp-per-row final LN + out proj ----------------
__global__ __launch_bounds__(256) void final_warp(
    const __half* __restrict__ in, const float* __restrict__ g,
    const float* __restrict__ b, const float* __restrict__ w,
    const float* __restrict__ bout, float* __restrict__ out)
{
    const int warp = threadIdx.x >> 5, lane = threadIdx.x & 31;
    const int row = blockIdx.x * 8 + warp;
    const uint4* src = (const uint4*)(in + (size_t)row * DM);
    uint4 v0 = src[lane];
    uint4 v1 = src[lane + 32];
    const __half2* h0 = (const __half2*)&v0;
    const __half2* h1 = (const __half2*)&v1;
    float f[16];
    float s = 0.f, sq = 0.f;
#pragma unroll
    for (int i = 0; i < 4; i++) {
        float2 a = __half22float2(h0[i]);
        float2 c = __half22float2(h1[i]);
        f[2 * i] = a.x; f[2 * i + 1] = a.y;
        f[8 + 2 * i] = c.x; f[8 + 2 * i + 1] = c.y;
        s += a.x + a.y + c.x + c.y;
        sq += a.x * a.x + a.y * a.y + c.x * c.x + c.y * c.y;
    }
#pragma unroll
    for (int o = 16; o > 0; o >>= 1) {
        s  += __shfl_xor_sync(0xffffffffu, s, o);
        sq += __shfl_xor_sync(0xffffffffu, sq, o);
    }
    float mu = s * (1.f / DM);
    float rstd = rsqrtf(sq * (1.f / DM) - mu * mu + EPS_LN);
    const float4* g4 = (const float4*)g;
    const float4* b4 = (const float4*)b;
    const float4* w4 = (const float4*)w;
    float acc = 0.f;
#pragma unroll
    for (int i = 0; i < 2; i++) {
        float4 gv = g4[lane * 2 + i];
        float4 bv = b4[lane * 2 + i];
        float4 wv = w4[lane * 2 + i];
        acc += ((f[4 * i]     - mu) * rstd * gv.x + bv.x) * wv.x
             + ((f[4 * i + 1] - mu) * rstd * gv.y + bv.y) * wv.y
             + ((f[4 * i + 2] - mu) * rstd * gv.z + bv.z) * wv.z
             + ((f[4 * i + 3] - mu) * rstd * gv.w + bv.w) * wv.w;
        float4 gw = g4[lane * 2 + 64 + i];
        float4 bw = b4[lane * 2 + 64 + i];
        float4 ww = w4[lane * 2 + 64 + i];
        acc += ((f[8 + 4 * i]     - mu) * rstd * gw.x + bw.x) * ww.x
             + ((f[8 + 4 * i + 1] - mu) * rstd * gw.y + bw.y) * ww.y
             + ((f[8 + 4 * i + 2] - mu) * rstd * gw.z + bw.z) * ww.z
             + ((f[8 + 4 * i + 3] - mu) * rstd * gw.w + bw.w) * ww.w;
    }
#pragma unroll
    for (int o = 16; o > 0; o >>= 1)
        acc += __shfl_xor_sync(0xffffffffu, acc, o);
    if (lane == 0) out[row] = acc + bout[0];
}

extern "C" void kernel_launch(void* const* d_in, const int* in_sizes, int n_in,
                              void* d_out, int out_size)
{
    const float* emb   = (const float*)d_in[0];
    const float* W0    = (const float*)d_in[1];
    const float* b0    = (const float*)d_in[2];
    const float* Wq    = (const float*)d_in[3];
    const float* bq    = (const float*)d_in[4];
    const float* Wk    = (const float*)d_in[5];
    const float* bk    = (const float*)d_in[6];
    const float* Wv    = (const float*)d_in[7];
    const float* bv    = (const float*)d_in[8];
    const float* Wo    = (const float*)d_in[9];
    const float* bo    = (const float*)d_in[10];
    const float* ln1s  = (const float*)d_in[11];
    const float* ln1b  = (const float*)d_in[12];
    const float* W1    = (const float*)d_in[13];
    const float* b1    = (const float*)d_in[14];
    const float* W2    = (const float*)d_in[15];
    const float* b2    = (const float*)d_in[16];
    const float* ln2s  = (const float*)d_in[17];
    const float* ln2b  = (const float*)d_in[18];
    const float* lnfs  = (const float*)d_in[19];
    const float* lnfb  = (const float*)d_in[20];
    const float* Wout  = (const float*)d_in[21];
    const float* bout  = (const float*)d_in[22];
    float* out = (float*)d_out;

    auto gemm_in   = gemm_t<10, DM,   0, 0, 1>;
    auto gemm_qkv  = gemm_t<8,  QKVN, 3, 0, 3>;
    auto gemm_wo   = gemm_t<8,  DM,   0, 2, 1>;
    auto gemm_ffn1 = gemm_t<8,  FF,   2, 0, 1>;
    auto gemm_ffn2 = gemm_t<16, DM,   0, 2, 1>;
    cudaFuncSetAttribute(gemm_in,   cudaFuncAttributeMaxDynamicSharedMemorySize, GEMM_SMEM);
    cudaFuncSetAttribute(gemm_qkv,  cudaFuncAttributeMaxDynamicSharedMemorySize, GEMM_SMEM);
    cudaFuncSetAttribute(gemm_wo,   cudaFuncAttributeMaxDynamicSharedMemorySize, GEMM_SMEM);
    cudaFuncSetAttribute(gemm_ffn1, cudaFuncAttributeMaxDynamicSharedMemorySize, GEMM_SMEM);
    cudaFuncSetAttribute(gemm_ffn2, cudaFuncAttributeMaxDynamicSharedMemorySize, GEMM_SMEM);

    __half *he, *hx, *hy, *hq, *ht, *hh, *kT, *vT, *kvx;
    __half *w0t, *wqkvt, *wot, *w1t, *w2t;
    float *pkvp, *bqkv;
    cudaGetSymbolAddress((void**)&he,  g_he);
    cudaGetSymbolAddress((void**)&hx,  g_hx);
    cudaGetSymbolAddress((void**)&hy,  g_hy);
    cudaGetSymbolAddress((void**)&hq,  g_hq);
    cudaGetSymbolAddress((void**)&ht,  g_ht);
    cudaGetSymbolAddress((void**)&hh,  g_hh);
    cudaGetSymbolAddress((void**)&kT,  g_kT);
    cudaGetSymbolAddress((void**)&vT,  g_vT);
    cudaGetSymbolAddress((void**)&kvx, g_kvx);
    cudaGetSymbolAddress((void**)&pkvp, g_kvpart);
    cudaGetSymbolAddress((void**)&w0t, g_w0t);
    cudaGetSymbolAddress((void**)&wqkvt, g_wqkvt);
    cudaGetSymbolAddress((void**)&wot, g_wot);
    cudaGetSymbolAddress((void**)&w1t, g_w1t);
    cudaGetSymbolAddress((void**)&w2t, g_w2t);
    cudaGetSymbolAddress((void**)&bqkv, g_bqkv);

    // ---- prep ----
    prep_all<<<(PREP_TOT + 255) / 256, 256>>>(emb, he, vT, bq, bk, bv, bqkv);

    TrPack pack;
    int tileOff = 0;
    auto addTr = [&](int idx, const float* in, __half* outp, int K, int N, int KP) {
        pack.d[idx].in = in; pack.d[idx].out = outp;
        pack.d[idx].K = K; pack.d[idx].N = N; pack.d[idx].KP = KP;
        pack.d[idx].tileStart = tileOff;
        tileOff += (KP / 32) * ((N + 31) / 32);
    };
    int di = 0;
    addTr(di++, W0, w0t, F_IN, DM, KPAD);
    for (int l = 0; l < NLAY; l++) {
        __half* wl = wqkvt + (size_t)l * QKVN * DM;
        addTr(di++, Wq + (size_t)l * DM * DM, wl,                        DM, DM, DM);
        addTr(di++, Wk + (size_t)l * DM * DM, wl + (size_t)DM * DM,      DM, DM, DM);
        addTr(di++, Wv + (size_t)l * DM * DM, wl + (size_t)2 * DM * DM,  DM, DM, DM);
        addTr(di++, Wo + (size_t)l * DM * DM, wot + (size_t)l * DM * DM, DM, DM, DM);
        addTr(di++, W1 + (size_t)l * DM * FF, w1t + (size_t)l * DM * FF, DM, FF, DM);
        addTr(di++, W2 + (size_t)l * FF * DM, w2t + (size_t)l * FF * DM, FF, DM, FF);
    }
    transpose_batch<<<tileOff, dim3(32, 8)>>>(pack);

    // ---- input projection -> hx fp16 ----
    gemm_in<<<dim3(DM / GBN, BS / GBM), 256, GEMM_SMEM>>>(
        he, w0t, b0, nullptr, hx, nullptr, nullptr);

    for (int l = 0; l < NLAY; l++) {
        const __half* wqkv_l = wqkvt + (size_t)l * QKVN * DM;
        const __half* wot_l  = wot + (size_t)l * DM * DM;
        const __half* w1t_l  = w1t + (size_t)l * DM * FF;
        const __half* w2t_l  = w2t + (size_t)l * FF * DM;
        const float* bqkv_l = bqkv + (size_t)l * QKVN;
        const float* bo_l = bo + (size_t)l * DM;
        const float* b1_l = b1 + (size_t)l * FF;
        const float* b2_l = b2 + (size_t)l * DM;

        gemm_qkv<<<dim3(QKVN / GBN, BS / GBM), 256, GEMM_SMEM>>>(
            hx, wqkv_l, bqkv_l, nullptr, hq, kT, vT);

        kv_mma<<<dim3(BH, NCHUNK), 128>>>(kT, vT, pkvp);
        reduce_kvx<<<BH, 256>>>(pkvp, kvx);
        attn_mma<<<dim3(BH, SEQ / 64), 128>>>(hq, kvx, ht);

        gemm_wo<<<dim3(DM / GBN, BS / GBM), 256, GEMM_SMEM>>>(
            ht, wot_l, bo_l, hx, hy, nullptr, nullptr);
        ln_warp<<<BS / 8, 256>>>(hy, ln1s + (size_t)l * DM, ln1b + (size_t)l * DM, hx);

        gemm_ffn1<<<dim3(FF / GBN, BS / GBM), 256, GEMM_SMEM>>>(
            hx, w1t_l, b1_l, nullptr, hh, nullptr, nullptr);
        gemm_ffn2<<<dim3(DM / GBN, BS / GBM), 256, GEMM_SMEM>>>(
            hh, w2t_l, b2_l, hx, hy, nullptr, nullptr);
        ln_warp<<<BS / 8, 256>>>(hy, ln2s + (size_t)l * DM, ln2b + (size_t)l * DM, hx);
    }

    final_warp<<<BS / 8, 256>>>(hx, lnfs, lnfb, Wout, bout, out);
}